// round 1
// baseline (speedup 1.0000x reference)
#include <cuda_runtime.h>
#include <cuda_bf16.h>
#include <math.h>

// Problem constants (fixed by the reference)
#define BATCH     65536
#define EMBED_DIM 128
#define NEG_K     5

#define WARPS_PER_BLOCK 8
#define BLOCK_THREADS   (WARPS_PER_BLOCK * 32)
#define NUM_BLOCKS      (BATCH / WARPS_PER_BLOCK)   // 8192

// Scratch for per-block partial sums (allocation-free per harness rules)
__device__ float g_partials[NUM_BLOCKS];

__device__ __forceinline__ float log_sigmoid(float x) {
    // stable: min(x,0) - log1p(exp(-|x|))
    return fminf(x, 0.0f) - log1pf(__expf(-fabsf(x)));
}

__global__ __launch_bounds__(BLOCK_THREADS)
void skipgram_loss_kernel(const int* __restrict__ center,
                          const int* __restrict__ context,
                          const int* __restrict__ negatives,
                          const float* __restrict__ u_weight,
                          const float* __restrict__ v_weight) {
    const int warp_in_block = threadIdx.x >> 5;
    const int lane          = threadIdx.x & 31;
    const int b             = blockIdx.x * WARPS_PER_BLOCK + warp_in_block;

    // ---- gather indices (broadcast loads: all lanes read same address) ----
    const int ci = center[b];
    const int xi = context[b];
    int ni[NEG_K];
#pragma unroll
    for (int k = 0; k < NEG_K; k++) ni[k] = negatives[b * NEG_K + k];

    // ---- issue all 7 row loads up front (MLP=7 per lane) ----
    const float4* cp = reinterpret_cast<const float4*>(u_weight + (size_t)ci * EMBED_DIM);
    const float4* xp = reinterpret_cast<const float4*>(v_weight + (size_t)xi * EMBED_DIM);
    float4 c4 = __ldg(cp + lane);
    float4 x4 = __ldg(xp + lane);
    float4 n4[NEG_K];
#pragma unroll
    for (int k = 0; k < NEG_K; k++) {
        const float4* np = reinterpret_cast<const float4*>(v_weight + (size_t)ni[k] * EMBED_DIM);
        n4[k] = __ldg(np + lane);
    }

    // ---- 6 partial dot products per lane ----
    float acc[1 + NEG_K];
    acc[0] = c4.x * x4.x + c4.y * x4.y + c4.z * x4.z + c4.w * x4.w;
#pragma unroll
    for (int k = 0; k < NEG_K; k++) {
        acc[1 + k] = c4.x * n4[k].x + c4.y * n4[k].y + c4.z * n4[k].z + c4.w * n4[k].w;
    }

    // ---- butterfly warp reduction of all 6 dots ----
#pragma unroll
    for (int off = 16; off > 0; off >>= 1) {
#pragma unroll
        for (int j = 0; j < 1 + NEG_K; j++) {
            acc[j] += __shfl_xor_sync(0xFFFFFFFFu, acc[j], off);
        }
    }

    // ---- per-element loss (every lane holds the full dots; lane 0 uses it) ----
    float loss = 0.0f;
    if (lane == 0) {
        float pos_loss = log_sigmoid(acc[0]);
        float neg_loss = 0.0f;
#pragma unroll
        for (int k = 0; k < NEG_K; k++) {
            neg_loss += log_sigmoid(-acc[1 + k]);
        }
        loss = -(pos_loss + neg_loss);
    }

    // ---- block reduction: one value per warp -> shared -> thread 0 ----
    __shared__ float smem[WARPS_PER_BLOCK];
    if (lane == 0) smem[warp_in_block] = loss;
    __syncthreads();
    if (threadIdx.x == 0) {
        float s = 0.0f;
#pragma unroll
        for (int w = 0; w < WARPS_PER_BLOCK; w++) s += smem[w];
        g_partials[blockIdx.x] = s;
    }
}

__global__ __launch_bounds__(256)
void final_reduce_kernel(float* __restrict__ out) {
    __shared__ double smem[256];
    double s = 0.0;
    for (int i = threadIdx.x; i < NUM_BLOCKS; i += 256) {
        s += (double)g_partials[i];
    }
    smem[threadIdx.x] = s;
    __syncthreads();
#pragma unroll
    for (int stride = 128; stride > 0; stride >>= 1) {
        if (threadIdx.x < stride) smem[threadIdx.x] += smem[threadIdx.x + stride];
        __syncthreads();
    }
    if (threadIdx.x == 0) {
        out[0] = (float)(smem[0] * (1.0 / (double)BATCH));
    }
}

extern "C" void kernel_launch(void* const* d_in, const int* in_sizes, int n_in,
                              void* d_out, int out_size) {
    // metadata order: center_nodes, context_nodes, negative_nodes, u_weight, v_weight
    const int*   center    = (const int*)d_in[0];
    const int*   context   = (const int*)d_in[1];
    const int*   negatives = (const int*)d_in[2];
    const float* u_weight  = (const float*)d_in[3];
    const float* v_weight  = (const float*)d_in[4];
    float*       out       = (float*)d_out;

    skipgram_loss_kernel<<<NUM_BLOCKS, BLOCK_THREADS>>>(center, context, negatives,
                                                        u_weight, v_weight);
    final_reduce_kernel<<<1, 256>>>(out);
}